// round 1
// baseline (speedup 1.0000x reference)
#include <cuda_runtime.h>

// LSTM(I=13,H=64,T=5) + MLP(64->64 relu ->13), B=262144 rows, fp32.
// Round 1: CUDA-core fp32 baseline. One thread = one batch row.
// Weights staged in SMEM, gate-interleaved so each (n,k) is one broadcast
// LDS.128 feeding 4 FFMAs. h[64] in registers; c / h-next round-trip through
// per-thread-private SMEM columns (no __syncthreads needed after preamble).

#define BTHREADS 256

// SMEM layout (floats):
//   wih4 : 64*13 float4  = 3328 f
//   whh4 : 64*64 float4  = 16384 f
//   bc4  : 64 float4     = 256 f
//   w1   : 64*64         = 4096 f
//   b1   : 64 f
//   w2   : 13*64         = 832 f
//   b2   : 16 f (padded)
//   cbuf : 64*256        = 16384 f
//   hbuf : 64*256        = 16384 f
// total = 57744 floats = 230976 bytes  (<= 232448 max per CTA)
#define SMEM_FLOATS 57744

__device__ __forceinline__ float fsig(float v) {
    return __fdividef(1.0f, 1.0f + __expf(-v));
}
__device__ __forceinline__ float ftanh_(float v) {
    v = fminf(fmaxf(v, -15.0f), 15.0f);
    float e = __expf(-2.0f * v);
    return __fdividef(1.0f - e, 1.0f + e);
}

extern __shared__ float smem[];

__global__ void __launch_bounds__(BTHREADS, 1)
lstm_fused_kernel(const float* __restrict__ x,
                  const float* __restrict__ W_ih,
                  const float* __restrict__ W_hh,
                  const float* __restrict__ b_ih,
                  const float* __restrict__ b_hh,
                  const float* __restrict__ W1,
                  const float* __restrict__ b1,
                  const float* __restrict__ W2,
                  const float* __restrict__ b2,
                  float* __restrict__ out,
                  int B)
{
    float4* s_wih = (float4*)smem;              // [64][13] gate-interleaved
    float4* s_whh = s_wih + 64 * 13;            // [64][64] gate-interleaved
    float4* s_bc  = s_whh + 64 * 64;            // [64]
    float*  s_w1  = (float*)(s_bc + 64);        // [64][64]
    float*  s_b1  = s_w1 + 4096;                // [64]
    float*  s_w2  = s_b1 + 64;                  // [13][64]
    float*  s_b2  = s_w2 + 832;                 // [16]
    float*  s_cb  = s_b2 + 16;                  // [64][256] per-thread columns
    float*  s_hb  = s_cb + 64 * 256;            // [64][256]

    const int tid = threadIdx.x;

    // ---- stage + reorganize weights (coalesced gmem reads) ----
    for (int idx = tid; idx < 64 * 13; idx += BTHREADS) {
        float4 v;
        v.x = W_ih[idx];
        v.y = W_ih[idx + 832];
        v.z = W_ih[idx + 1664];
        v.w = W_ih[idx + 2496];
        s_wih[idx] = v;
    }
    for (int idx = tid; idx < 64 * 64; idx += BTHREADS) {
        float4 v;
        v.x = W_hh[idx];
        v.y = W_hh[idx + 4096];
        v.z = W_hh[idx + 8192];
        v.w = W_hh[idx + 12288];
        s_whh[idx] = v;
    }
    if (tid < 64) {
        float4 v;
        v.x = b_ih[tid]       + b_hh[tid];
        v.y = b_ih[tid + 64]  + b_hh[tid + 64];
        v.z = b_ih[tid + 128] + b_hh[tid + 128];
        v.w = b_ih[tid + 192] + b_hh[tid + 192];
        s_bc[tid] = v;
    }
    for (int idx = tid; idx < 4096; idx += BTHREADS) s_w1[idx] = W1[idx];
    for (int idx = tid; idx < 832;  idx += BTHREADS) s_w2[idx] = W2[idx];
    if (tid < 64) s_b1[tid] = b1[tid];
    if (tid < 16) s_b2[tid] = (tid < 13) ? b2[tid] : 0.0f;
    __syncthreads();

    const int b = blockIdx.x * BTHREADS + tid;
    if (b >= B) return;

    const float* xr = x + (size_t)b * 65;   // T*I = 65

    float h[64];
#pragma unroll
    for (int k = 0; k < 64; k++) h[k] = 0.0f;
#pragma unroll
    for (int k = 0; k < 64; k++) s_cb[k * 256 + tid] = 0.0f;

    // ---- 5 recurrent steps ----
#pragma unroll 1
    for (int t = 0; t < 5; t++) {
        float xv[13];
#pragma unroll
        for (int i = 0; i < 13; i++) xv[i] = xr[t * 13 + i];

#pragma unroll 1
        for (int n = 0; n < 64; n++) {
            float4 bc = s_bc[n];
            float ai = bc.x, af = bc.y, ag = bc.z, ao = bc.w;

            const float4* wi = s_wih + n * 13;
#pragma unroll
            for (int i = 0; i < 13; i++) {
                float4 w = wi[i];
                ai = fmaf(w.x, xv[i], ai);
                af = fmaf(w.y, xv[i], af);
                ag = fmaf(w.z, xv[i], ag);
                ao = fmaf(w.w, xv[i], ao);
            }

            const float4* wh = s_whh + n * 64;
#pragma unroll
            for (int k = 0; k < 64; k++) {
                float4 w = wh[k];
                ai = fmaf(w.x, h[k], ai);
                af = fmaf(w.y, h[k], af);
                ag = fmaf(w.z, h[k], ag);
                ao = fmaf(w.w, h[k], ao);
            }

            float c_old = s_cb[n * 256 + tid];
            float cn = fsig(af) * c_old + fsig(ai) * ftanh_(ag);
            s_cb[n * 256 + tid] = cn;
            s_hb[n * 256 + tid] = fsig(ao) * ftanh_(cn);
        }

#pragma unroll
        for (int k = 0; k < 64; k++) h[k] = s_hb[k * 256 + tid];
    }

    // ---- MLP layer 1: z = relu(h @ W1^T + b1) ----
#pragma unroll 1
    for (int j = 0; j < 64; j++) {
        float a = s_b1[j];
        const float4* w = (const float4*)(s_w1 + j * 64);
#pragma unroll
        for (int k = 0; k < 16; k++) {
            float4 wv = w[k];
            a = fmaf(wv.x, h[4 * k + 0], a);
            a = fmaf(wv.y, h[4 * k + 1], a);
            a = fmaf(wv.z, h[4 * k + 2], a);
            a = fmaf(wv.w, h[4 * k + 3], a);
        }
        s_hb[j * 256 + tid] = fmaxf(a, 0.0f);
    }

    float z[64];
#pragma unroll
    for (int k = 0; k < 64; k++) z[k] = s_hb[k * 256 + tid];

    // ---- MLP layer 2: out = z @ W2^T + b2 ----
    float* o_ptr = out + (size_t)b * 13;
#pragma unroll 1
    for (int o = 0; o < 13; o++) {
        float a = s_b2[o];
        const float4* w = (const float4*)(s_w2 + o * 64);
#pragma unroll
        for (int k = 0; k < 16; k++) {
            float4 wv = w[k];
            a = fmaf(wv.x, z[4 * k + 0], a);
            a = fmaf(wv.y, z[4 * k + 1], a);
            a = fmaf(wv.z, z[4 * k + 2], a);
            a = fmaf(wv.w, z[4 * k + 3], a);
        }
        o_ptr[o] = a;
    }
}

extern "C" void kernel_launch(void* const* d_in, const int* in_sizes, int n_in,
                              void* d_out, int out_size)
{
    const float* x    = (const float*)d_in[0];
    const float* W_ih = (const float*)d_in[1];
    const float* W_hh = (const float*)d_in[2];
    const float* b_ih = (const float*)d_in[3];
    const float* b_hh = (const float*)d_in[4];
    const float* W1   = (const float*)d_in[5];
    const float* b1   = (const float*)d_in[6];
    const float* W2   = (const float*)d_in[7];
    const float* b2   = (const float*)d_in[8];
    float* out = (float*)d_out;

    const int B = in_sizes[0] / 65;   // T*I = 65 floats per row
    const int smem_bytes = SMEM_FLOATS * 4;

    cudaFuncSetAttribute(lstm_fused_kernel,
                         cudaFuncAttributeMaxDynamicSharedMemorySize, smem_bytes);

    const int grid = (B + BTHREADS - 1) / BTHREADS;
    lstm_fused_kernel<<<grid, BTHREADS, smem_bytes>>>(
        x, W_ih, W_hh, b_ih, b_hh, W1, b1, W2, b2, out, B);
}

// round 3
// speedup vs baseline: 1.8647x; 1.8647x over previous
#include <cuda_runtime.h>

// LSTM(I=13,H=64,T=5) + MLP(64->64 relu ->13), B=262144 rows, fp32.
// Round 2: gate-pair packed f32x2 math. One thread = one batch row.
// Weight quads (i,f,g,o) per (n,k) sit gate-interleaved in SMEM, so the two
// 64-bit halves of each LDS.128 are ready-made packed operands (w_i,w_f) and
// (w_g,w_o). h[k] / x[i] are duplicated into both f32x2 lanes once per step.
// Per weight quad: 1 LDS.128 + 2 fma.rn.f32x2  (was 1 LDS.128 + 4 FFMA).

#define BTHREADS 256
#define SMEM_FLOATS 57744   // same layout as round 1: 230976 bytes

typedef unsigned long long u64;

__device__ __forceinline__ u64 pack2(float a, float b) {
    u64 r; asm("mov.b64 %0, {%1, %2};" : "=l"(r) : "f"(a), "f"(b)); return r;
}
__device__ __forceinline__ u64 dup2(float a) {
    u64 r; asm("mov.b64 %0, {%1, %1};" : "=l"(r) : "f"(a)); return r;
}
__device__ __forceinline__ void unpack2(u64 v, float& a, float& b) {
    asm("mov.b64 {%0, %1}, %2;" : "=f"(a), "=f"(b) : "l"(v));
}
__device__ __forceinline__ void fma2(u64& d, u64 a, u64 b) {
    asm("fma.rn.f32x2 %0, %1, %2, %0;" : "+l"(d) : "l"(a), "l"(b));
}

__device__ __forceinline__ float fsig(float v) {
    return __fdividef(1.0f, 1.0f + __expf(-v));
}
__device__ __forceinline__ float ftanh_(float v) {
    v = fminf(fmaxf(v, -15.0f), 15.0f);
    float e = __expf(-2.0f * v);
    return __fdividef(1.0f - e, 1.0f + e);
}

extern __shared__ float smem[];

__global__ void __launch_bounds__(BTHREADS, 1)
lstm_fused_kernel(const float* __restrict__ x,
                  const float* __restrict__ W_ih,
                  const float* __restrict__ W_hh,
                  const float* __restrict__ b_ih,
                  const float* __restrict__ b_hh,
                  const float* __restrict__ W1,
                  const float* __restrict__ b1,
                  const float* __restrict__ W2,
                  const float* __restrict__ b2,
                  float* __restrict__ out,
                  int B)
{
    float4* s_wih = (float4*)smem;              // [64][13] gate-interleaved (i,f,g,o)
    float4* s_whh = s_wih + 64 * 13;            // [64][64] gate-interleaved
    float4* s_bc  = s_whh + 64 * 64;            // [64]
    float*  s_w1  = (float*)(s_bc + 64);        // [64][64]
    float*  s_b1  = s_w1 + 4096;                // [64]
    float*  s_w2  = s_b1 + 64;                  // [13][64]
    float*  s_b2  = s_w2 + 832;                 // [16]
    float*  s_cb  = s_b2 + 16;                  // [64][256] per-thread columns
    float*  s_hb  = s_cb + 64 * 256;            // [64][256]

    const int tid = threadIdx.x;

    // ---- stage + reorganize weights (coalesced gmem reads) ----
    for (int idx = tid; idx < 64 * 13; idx += BTHREADS) {
        float4 v;
        v.x = W_ih[idx];
        v.y = W_ih[idx + 832];
        v.z = W_ih[idx + 1664];
        v.w = W_ih[idx + 2496];
        s_wih[idx] = v;
    }
    for (int idx = tid; idx < 64 * 64; idx += BTHREADS) {
        float4 v;
        v.x = W_hh[idx];
        v.y = W_hh[idx + 4096];
        v.z = W_hh[idx + 8192];
        v.w = W_hh[idx + 12288];
        s_whh[idx] = v;
    }
    if (tid < 64) {
        float4 v;
        v.x = b_ih[tid]       + b_hh[tid];
        v.y = b_ih[tid + 64]  + b_hh[tid + 64];
        v.z = b_ih[tid + 128] + b_hh[tid + 128];
        v.w = b_ih[tid + 192] + b_hh[tid + 192];
        s_bc[tid] = v;
    }
    for (int idx = tid; idx < 4096; idx += BTHREADS) s_w1[idx] = W1[idx];
    for (int idx = tid; idx < 832;  idx += BTHREADS) s_w2[idx] = W2[idx];
    if (tid < 64) s_b1[tid] = b1[tid];
    if (tid < 16) s_b2[tid] = (tid < 13) ? b2[tid] : 0.0f;
    __syncthreads();

    const int b = blockIdx.x * BTHREADS + tid;
    if (b >= B) return;

    const float* xr = x + (size_t)b * 65;   // T*I = 65

    u64 h2[64];                              // h[k] duplicated into both lanes
#pragma unroll
    for (int k = 0; k < 64; k++) h2[k] = 0ULL;
#pragma unroll
    for (int k = 0; k < 64; k++) s_cb[k * 256 + tid] = 0.0f;

    // ---- 5 recurrent steps ----
#pragma unroll 1
    for (int t = 0; t < 5; t++) {
        u64 xv2[13];
#pragma unroll
        for (int i = 0; i < 13; i++) xv2[i] = dup2(xr[t * 13 + i]);

#pragma unroll 1
        for (int n = 0; n < 64; n++) {
            float4 bc = s_bc[n];
            u64 aif = pack2(bc.x, bc.y);     // (a_i, a_f)
            u64 ago = pack2(bc.z, bc.w);     // (a_g, a_o)

            const ulonglong2* wi =
                reinterpret_cast<const ulonglong2*>(s_wih + n * 13);
#pragma unroll
            for (int i = 0; i < 13; i++) {
                ulonglong2 w = wi[i];        // LDS.128: (w_i,w_f),(w_g,w_o)
                fma2(aif, w.x, xv2[i]);
                fma2(ago, w.y, xv2[i]);
            }

            const ulonglong2* wh =
                reinterpret_cast<const ulonglong2*>(s_whh + n * 64);
#pragma unroll
            for (int k = 0; k < 64; k++) {
                ulonglong2 w = wh[k];
                fma2(aif, w.x, h2[k]);
                fma2(ago, w.y, h2[k]);
            }

            float ai, af, ag, ao;
            unpack2(aif, ai, af);
            unpack2(ago, ag, ao);

            float c_old = s_cb[n * 256 + tid];
            float cn = fsig(af) * c_old + fsig(ai) * ftanh_(ag);
            s_cb[n * 256 + tid] = cn;
            s_hb[n * 256 + tid] = fsig(ao) * ftanh_(cn);
        }

#pragma unroll
        for (int k = 0; k < 64; k++) h2[k] = dup2(s_hb[k * 256 + tid]);
    }

    // ---- MLP layer 1: z = relu(h @ W1^T + b1) ----
    float h[64];
#pragma unroll
    for (int k = 0; k < 64; k++) h[k] = s_hb[k * 256 + tid];

#pragma unroll 1
    for (int j = 0; j < 64; j++) {
        float a = s_b1[j];
        const float4* w = (const float4*)(s_w1 + j * 64);
#pragma unroll
        for (int k = 0; k < 16; k++) {
            float4 wv = w[k];
            a = fmaf(wv.x, h[4 * k + 0], a);
            a = fmaf(wv.y, h[4 * k + 1], a);
            a = fmaf(wv.z, h[4 * k + 2], a);
            a = fmaf(wv.w, h[4 * k + 3], a);
        }
        s_hb[j * 256 + tid] = fmaxf(a, 0.0f);
    }

    float z[64];
#pragma unroll
    for (int k = 0; k < 64; k++) z[k] = s_hb[k * 256 + tid];

    // ---- MLP layer 2: out = z @ W2^T + b2 ----
    float* o_ptr = out + (size_t)b * 13;
#pragma unroll 1
    for (int o = 0; o < 13; o++) {
        float a = s_b2[o];
        const float4* w = (const float4*)(s_w2 + o * 64);
#pragma unroll
        for (int k = 0; k < 16; k++) {
            float4 wv = w[k];
            a = fmaf(wv.x, z[4 * k + 0], a);
            a = fmaf(wv.y, z[4 * k + 1], a);
            a = fmaf(wv.z, z[4 * k + 2], a);
            a = fmaf(wv.w, z[4 * k + 3], a);
        }
        o_ptr[o] = a;
    }
}

extern "C" void kernel_launch(void* const* d_in, const int* in_sizes, int n_in,
                              void* d_out, int out_size)
{
    const float* x    = (const float*)d_in[0];
    const float* W_ih = (const float*)d_in[1];
    const float* W_hh = (const float*)d_in[2];
    const float* b_ih = (const float*)d_in[3];
    const float* b_hh = (const float*)d_in[4];
    const float* W1   = (const float*)d_in[5];
    const float* b1   = (const float*)d_in[6];
    const float* W2   = (const float*)d_in[7];
    const float* b2   = (const float*)d_in[8];
    float* out = (float*)d_out;

    const int B = in_sizes[0] / 65;   // T*I = 65 floats per row
    const int smem_bytes = SMEM_FLOATS * 4;

    cudaFuncSetAttribute(lstm_fused_kernel,
                         cudaFuncAttributeMaxDynamicSharedMemorySize, smem_bytes);

    const int grid = (B + BTHREADS - 1) / BTHREADS;
    lstm_fused_kernel<<<grid, BTHREADS, smem_bytes>>>(
        x, W_ih, W_hh, b_ih, b_hh, W1, b1, W2, b2, out, B);
}